// round 16
// baseline (speedup 1.0000x reference)
#include <cuda_runtime.h>

#define INF 6
#define OUTF 64
#define NCELLS (512 * 512)
#define CAP 64
static constexpr float BN_EPS = 1e-5f;

// ---- device scratch (static arrays only; no allocations) ----
__device__ double g_mom[27];            // [0..5]=sum x_k ; [6..26]=upper-tri sum x_a x_b
__device__ float  g_Wc[INF][OUTF];      // scale_j * W[j][k], stored [k][j]
__device__ float  g_c[OUTF];            // beta_j + scale_j*(b_j - mean_j)
__device__ int    g_dtype;              // 1 => indices are int64 pairs
__device__ int    g_count[NCELLS];      // points per cell
__device__ int    g_ids[NCELLS * CAP];  // 64 MB: point-id lists per cell
__device__ int    g_ovf[8192];          // overflow point ids (expected empty)
__device__ int    g_ovfn;

typedef unsigned long long u64;
__device__ __forceinline__ u64 pk2(float lo, float hi) {
    u64 r; asm("mov.b64 %0,{%1,%2};" : "=l"(r) : "f"(lo), "f"(hi)); return r;
}
__device__ __forceinline__ void up2(u64 v, float& lo, float& hi) {
    asm("mov.b64 {%0,%1},%2;" : "=f"(lo), "=f"(hi) : "l"(v));
}
__device__ __forceinline__ u64 fma2(u64 a, u64 b, u64 c) {
    u64 d; asm("fma.rn.f32x2 %0,%1,%2,%3;" : "=l"(d) : "l"(a), "l"(b), "l"(c)); return d;
}

// ---------------------------------------------------------------------------
// K0: zero counters/moments, detect index dtype (int64 pairs have zero odd words)
// launch <<<256,256>>> : exactly 65536 threads zero 65536 int4 of g_count
// ---------------------------------------------------------------------------
__global__ void k_init(const unsigned int* __restrict__ idxw, int nwords) {
    int t = blockIdx.x * blockDim.x + threadIdx.x;
    ((int4*)g_count)[t] = make_int4(0, 0, 0, 0);
    if (blockIdx.x == 0) {
        if (threadIdx.x < 27) g_mom[threadIdx.x] = 0.0;
        if (threadIdx.x == 31) g_ovfn = 0;
        unsigned acc = 0;
        for (int i = threadIdx.x; i < 4096; i += 256) {
            int w = 2 * i + 1;
            if (w < nwords) acc |= idxw[w];
        }
        #pragma unroll
        for (int o = 16; o > 0; o >>= 1) acc |= __shfl_down_sync(0xffffffffu, acc, o);
        __shared__ unsigned sacc[8];
        if ((threadIdx.x & 31) == 0) sacc[threadIdx.x >> 5] = acc;
        __syncthreads();
        if (threadIdx.x == 0) {
            unsigned a = 0;
            for (int w = 0; w < 8; w++) a |= sacc[w];
            g_dtype = (a == 0) ? 1 : 0;
        }
    }
}

// ---------------------------------------------------------------------------
// K1: fused moments + binning. Reads x (48MB) + idx (16/32MB) once.
// ---------------------------------------------------------------------------
__global__ void __launch_bounds__(256) k_moments_bin(const float* __restrict__ x,
                                                     const void* __restrict__ idx, int n) {
    float s[27];
    #pragma unroll
    for (int i = 0; i < 27; i++) s[i] = 0.f;
    int is64 = g_dtype;

    int stride = gridDim.x * blockDim.x;
    for (int i = blockIdx.x * blockDim.x + threadIdx.x; i < n; i += stride) {
        const float2* p = (const float2*)(x + (size_t)i * INF);
        float2 a = p[0], b = p[1], c = p[2];
        float v[6] = {a.x, a.y, b.x, b.y, c.x, c.y};
        int t = 6;
        #pragma unroll
        for (int A = 0; A < 6; A++) {
            s[A] += v[A];
            #pragma unroll
            for (int B = A; B < 6; B++) s[t++] += v[A] * v[B];
        }
        int ix, iy;
        if (is64) {
            longlong2 id = ((const longlong2*)idx)[i];
            ix = (int)id.x; iy = (int)id.y;
        } else {
            int2 id = ((const int2*)idx)[i];
            ix = id.x; iy = id.y;
        }
        int cell = (ix << 9) | iy;
        int slot = atomicAdd(&g_count[cell], 1);
        if (slot < CAP) {
            g_ids[(cell << 6) + slot] = i;
        } else {
            int o = atomicAdd(&g_ovfn, 1);
            if (o < 8192) g_ovf[o] = i;
        }
    }
    // reduce 27 moment partials
    #pragma unroll
    for (int i = 0; i < 27; i++) {
        #pragma unroll
        for (int off = 16; off > 0; off >>= 1)
            s[i] += __shfl_down_sync(0xffffffffu, s[i], off);
    }
    __shared__ float part[27][8];
    int lane = threadIdx.x & 31, warp = threadIdx.x >> 5;
    if (lane == 0) {
        #pragma unroll
        for (int i = 0; i < 27; i++) part[i][warp] = s[i];
    }
    __syncthreads();
    if (threadIdx.x < 27) {
        float tot = 0.f;
        int nw = blockDim.x >> 5;
        for (int w = 0; w < nw; w++) tot += part[threadIdx.x][w];
        atomicAdd(&g_mom[threadIdx.x], (double)tot);
    }
}

// ---------------------------------------------------------------------------
// K2: fold BN into per-feature affine (unchanged from passing version)
// ---------------------------------------------------------------------------
__global__ void k_finalize(const float* __restrict__ W, const float* __restrict__ b,
                           const float* __restrict__ gamma, const float* __restrict__ beta,
                           double inv_n) {
    int j = threadIdx.x;
    if (j >= OUTF) return;
    double S[6], M[21], w[6];
    for (int k = 0; k < 6; k++)  S[k] = g_mom[k];
    for (int t = 0; t < 21; t++) M[t] = g_mom[6 + t];
    for (int k = 0; k < 6; k++)  w[k] = (double)W[j * 6 + k];
    double bj = (double)b[j];

    double dot = 0.0;
    for (int k = 0; k < 6; k++) dot += w[k] * S[k];
    double q = 0.0; int t = 0;
    for (int A = 0; A < 6; A++)
        for (int B = A; B < 6; B++) {
            double term = w[A] * w[B] * M[t++];
            q += (A == B) ? term : 2.0 * term;
        }
    double mean = dot * inv_n + bj;
    double e2   = (q + 2.0 * bj * dot) * inv_n + bj * bj;
    double var  = e2 - mean * mean;
    double scale = (double)gamma[j] / sqrt(var + (double)BN_EPS);

    for (int k = 0; k < 6; k++) g_Wc[k][j] = (float)(scale * w[k]);
    g_c[j] = (float)((double)beta[j] + scale * (bj - mean));
}

// ---------------------------------------------------------------------------
// K3: gather. 8 threads per cell (8 features each = 4 f32x2 pairs).
// Block = 256 threads = 32 cells. Ids staged via smem; x prefetched one ahead.
// Every cell written unconditionally -> no memset of d_out needed.
// ---------------------------------------------------------------------------
__global__ void __launch_bounds__(256) k_gather(const float* __restrict__ x,
                                                float* __restrict__ out) {
    __shared__ int    s_ids[32 * CAP];          // 8 KB
    __shared__ float2 sW[INF][OUTF / 2];        // weight pairs
    __shared__ float2 sc2[OUTF / 2];
    __shared__ int    s_cnt[32];

    int tid = threadIdx.x;
    for (int t = tid; t < INF * OUTF / 2; t += 256)
        ((float2*)sW)[t] = ((const float2*)g_Wc)[t];
    if (tid < OUTF / 2) sc2[tid] = ((const float2*)g_c)[tid];

    int cell0 = blockIdx.x * 32;
    const int4* src = (const int4*)&g_ids[cell0 << 6];
    #pragma unroll
    for (int t = tid; t < 32 * CAP / 4; t += 256)
        ((int4*)s_ids)[t] = src[t];
    if (tid < 32) {
        int c = g_count[cell0 + tid];
        s_cnt[tid] = c < CAP ? c : CAP;
    }
    __syncthreads();

    int lc   = tid >> 3;          // local cell 0..31
    int part = tid & 7;           // feature block: feats [8*part, 8*part+8)
    int cell = cell0 + lc;
    int cnt  = s_cnt[lc];
    int pb   = part * 4;          // first f32x2 pair index

    u64 w0[6], w1[6], w2[6], w3[6];
    #pragma unroll
    for (int k = 0; k < 6; k++) {
        w0[k] = *(const u64*)&sW[k][pb + 0];
        w1[k] = *(const u64*)&sW[k][pb + 1];
        w2[k] = *(const u64*)&sW[k][pb + 2];
        w3[k] = *(const u64*)&sW[k][pb + 3];
    }
    u64 cp0 = *(const u64*)&sc2[pb + 0];
    u64 cp1 = *(const u64*)&sc2[pb + 1];
    u64 cp2 = *(const u64*)&sc2[pb + 2];
    u64 cp3 = *(const u64*)&sc2[pb + 3];

    float a0 = 0.f, a1 = 0.f, a2 = 0.f, a3 = 0.f, a4 = 0.f, a5 = 0.f, a6 = 0.f, a7 = 0.f;

    float2 xa, xb, xc;
    if (cnt > 0) {
        int id0 = s_ids[lc << 6];
        const float2* q = (const float2*)(x + (size_t)id0 * INF);
        xa = q[0]; xb = q[1]; xc = q[2];
    }
    for (int p = 0; p < cnt; p++) {
        int pn = (p + 1 < cnt) ? p + 1 : p;          // branch-free prefetch clamp
        int idn = s_ids[(lc << 6) + pn];
        const float2* q = (const float2*)(x + (size_t)idn * INF);
        float2 na = q[0], nb = q[1], nc = q[2];      // in flight during compute

        u64 t0 = cp0, t1 = cp1, t2 = cp2, t3 = cp3;
        float v0 = xa.x, v1 = xa.y, v2 = xb.x, v3 = xb.y, v4 = xc.x, v5 = xc.y;
        u64 vv;
        vv = pk2(v0, v0); t0 = fma2(vv, w0[0], t0); t1 = fma2(vv, w1[0], t1); t2 = fma2(vv, w2[0], t2); t3 = fma2(vv, w3[0], t3);
        vv = pk2(v1, v1); t0 = fma2(vv, w0[1], t0); t1 = fma2(vv, w1[1], t1); t2 = fma2(vv, w2[1], t2); t3 = fma2(vv, w3[1], t3);
        vv = pk2(v2, v2); t0 = fma2(vv, w0[2], t0); t1 = fma2(vv, w1[2], t1); t2 = fma2(vv, w2[2], t2); t3 = fma2(vv, w3[2], t3);
        vv = pk2(v3, v3); t0 = fma2(vv, w0[3], t0); t1 = fma2(vv, w1[3], t1); t2 = fma2(vv, w2[3], t2); t3 = fma2(vv, w3[3], t3);
        vv = pk2(v4, v4); t0 = fma2(vv, w0[4], t0); t1 = fma2(vv, w1[4], t1); t2 = fma2(vv, w2[4], t2); t3 = fma2(vv, w3[4], t3);
        vv = pk2(v5, v5); t0 = fma2(vv, w0[5], t0); t1 = fma2(vv, w1[5], t1); t2 = fma2(vv, w2[5], t2); t3 = fma2(vv, w3[5], t3);

        float lo, hi;
        up2(t0, lo, hi); a0 += fmaxf(lo, 0.f); a1 += fmaxf(hi, 0.f);
        up2(t1, lo, hi); a2 += fmaxf(lo, 0.f); a3 += fmaxf(hi, 0.f);
        up2(t2, lo, hi); a4 += fmaxf(lo, 0.f); a5 += fmaxf(hi, 0.f);
        up2(t3, lo, hi); a6 += fmaxf(lo, 0.f); a7 += fmaxf(hi, 0.f);

        xa = na; xb = nb; xc = nc;
    }

    float4* o = (float4*)(out + ((size_t)cell << 6) + (part << 3));
    o[0] = make_float4(a0, a1, a2, a3);
    o[1] = make_float4(a4, a5, a6, a7);
}

// ---------------------------------------------------------------------------
// K4: overflow points (expected none) — red.v4 onto the already-written grid
// ---------------------------------------------------------------------------
__global__ void k_overflow(const float* __restrict__ x, const void* __restrict__ idx,
                           float* __restrict__ out) {
    int nov = g_ovfn; if (nov > 8192) nov = 8192;
    int is64 = g_dtype;
    for (int e = blockIdx.x * blockDim.x + threadIdx.x; e < nov;
         e += gridDim.x * blockDim.x) {
        int i = g_ovf[e];
        const float2* p = (const float2*)(x + (size_t)i * INF);
        float2 a = p[0], b = p[1], c = p[2];
        float v[6] = {a.x, a.y, b.x, b.y, c.x, c.y};
        int ix, iy;
        if (is64) {
            longlong2 id = ((const longlong2*)idx)[i];
            ix = (int)id.x; iy = (int)id.y;
        } else {
            int2 id = ((const int2*)idx)[i];
            ix = id.x; iy = id.y;
        }
        float* cellp = out + (size_t)((ix << 9) | iy) * OUTF;
        for (int jg = 0; jg < OUTF / 4; jg++) {
            int j = jg * 4;
            float4 acc = *(const float4*)&g_c[j];
            for (int k = 0; k < 6; k++) {
                acc.x = fmaf(v[k], g_Wc[k][j + 0], acc.x);
                acc.y = fmaf(v[k], g_Wc[k][j + 1], acc.y);
                acc.z = fmaf(v[k], g_Wc[k][j + 2], acc.z);
                acc.w = fmaf(v[k], g_Wc[k][j + 3], acc.w);
            }
            acc.x = fmaxf(acc.x, 0.f); acc.y = fmaxf(acc.y, 0.f);
            acc.z = fmaxf(acc.z, 0.f); acc.w = fmaxf(acc.w, 0.f);
            asm volatile("red.global.add.v4.f32 [%0], {%1, %2, %3, %4};"
                         :: "l"(cellp + j), "f"(acc.x), "f"(acc.y), "f"(acc.z), "f"(acc.w)
                         : "memory");
        }
    }
}

// ---------------------------------------------------------------------------
extern "C" void kernel_launch(void* const* d_in, const int* in_sizes, int n_in,
                              void* d_out, int out_size) {
    const float* x     = (const float*)d_in[0];
    const void*  idx   = d_in[1];
    const float* W     = (const float*)d_in[2];
    const float* b     = (const float*)d_in[3];
    const float* gamma = (const float*)d_in[4];
    const float* beta  = (const float*)d_in[5];
    float* out = (float*)d_out;

    int n = in_sizes[0] / INF;
    int nwords = 2 * n; if (nwords > 8192) nwords = 8192;

    k_init<<<256, 256>>>((const unsigned int*)idx, nwords);
    k_moments_bin<<<1184, 256>>>(x, idx, n);
    k_finalize<<<1, 64>>>(W, b, gamma, beta, 1.0 / (double)n);
    k_gather<<<NCELLS * 8 / 256, 256>>>(x, out);
    k_overflow<<<16, 256>>>(x, idx, out);
}

// round 17
// speedup vs baseline: 1.6150x; 1.6150x over previous
#include <cuda_runtime.h>

#define INF 6
#define OUTF 64
#define NCELLS (512 * 512)
#define CAP 64
static constexpr float BN_EPS = 1e-5f;

// ---- device scratch (static arrays only; no allocations) ----
__device__ double g_mom[27];            // [0..5]=sum x_k ; [6..26]=upper-tri sum x_a x_b
__device__ float  g_Wc[INF][OUTF];      // scale_j * W[j][k], stored [k][j]
__device__ float  g_c[OUTF];            // beta_j + scale_j*(b_j - mean_j)
__device__ int    g_dtype;              // 1 => indices are int64 pairs
__device__ int    g_count[NCELLS];      // points per cell
__device__ float  g_pay[(size_t)NCELLS * CAP * 8];  // 512MB: 32B payload per slot
__device__ int    g_ovf[8192];          // overflow point ids (expected empty)
__device__ int    g_ovfn;

typedef unsigned long long u64;
__device__ __forceinline__ u64 pk2(float lo, float hi) {
    u64 r; asm("mov.b64 %0,{%1,%2};" : "=l"(r) : "f"(lo), "f"(hi)); return r;
}
__device__ __forceinline__ void up2(u64 v, float& lo, float& hi) {
    asm("mov.b64 {%0,%1},%2;" : "=f"(lo), "=f"(hi) : "l"(v));
}
__device__ __forceinline__ u64 fma2(u64 a, u64 b, u64 c) {
    u64 d; asm("fma.rn.f32x2 %0,%1,%2,%3;" : "=l"(d) : "l"(a), "l"(b), "l"(c)); return d;
}

// ---------------------------------------------------------------------------
// K0: zero counters/moments, detect index dtype (int64 pairs have zero odd words)
// launch <<<256,256>>>: 65536 threads zero 65536 int4 of g_count
// ---------------------------------------------------------------------------
__global__ void k_init(const unsigned int* __restrict__ idxw, int nwords) {
    int t = blockIdx.x * blockDim.x + threadIdx.x;
    ((int4*)g_count)[t] = make_int4(0, 0, 0, 0);
    if (blockIdx.x == 0) {
        if (threadIdx.x < 27) g_mom[threadIdx.x] = 0.0;
        if (threadIdx.x == 31) g_ovfn = 0;
        unsigned acc = 0;
        for (int i = threadIdx.x; i < 4096; i += 256) {
            int w = 2 * i + 1;
            if (w < nwords) acc |= idxw[w];
        }
        #pragma unroll
        for (int o = 16; o > 0; o >>= 1) acc |= __shfl_down_sync(0xffffffffu, acc, o);
        __shared__ unsigned sacc[8];
        if ((threadIdx.x & 31) == 0) sacc[threadIdx.x >> 5] = acc;
        __syncthreads();
        if (threadIdx.x == 0) {
            unsigned a = 0;
            for (int w = 0; w < 8; w++) a |= sacc[w];
            g_dtype = (a == 0) ? 1 : 0;
        }
    }
}

// ---------------------------------------------------------------------------
// K1: fused moments + payload binning. Reads x + idx once; writes 32B/point bins.
// ---------------------------------------------------------------------------
__global__ void __launch_bounds__(256) k_moments_bin(const float* __restrict__ x,
                                                     const void* __restrict__ idx, int n) {
    float s[27];
    #pragma unroll
    for (int i = 0; i < 27; i++) s[i] = 0.f;
    int is64 = g_dtype;

    int stride = gridDim.x * blockDim.x;
    for (int i = blockIdx.x * blockDim.x + threadIdx.x; i < n; i += stride) {
        const float2* p = (const float2*)(x + (size_t)i * INF);
        float2 a = p[0], b = p[1], c = p[2];
        float v[6] = {a.x, a.y, b.x, b.y, c.x, c.y};
        int t = 6;
        #pragma unroll
        for (int A = 0; A < 6; A++) {
            s[A] += v[A];
            #pragma unroll
            for (int B = A; B < 6; B++) s[t++] += v[A] * v[B];
        }
        int ix, iy;
        if (is64) {
            longlong2 id = ((const longlong2*)idx)[i];
            ix = (int)id.x; iy = (int)id.y;
        } else {
            int2 id = ((const int2*)idx)[i];
            ix = id.x; iy = id.y;
        }
        int cell = (ix << 9) | iy;
        int slot = atomicAdd(&g_count[cell], 1);
        if (slot < CAP) {
            float4* dst = (float4*)(g_pay + (((size_t)cell << 6) + slot) * 8);
            dst[0] = make_float4(v[0], v[1], v[2], v[3]);
            dst[1] = make_float4(v[4], v[5], 0.f, 0.f);
        } else {
            int o = atomicAdd(&g_ovfn, 1);
            if (o < 8192) g_ovf[o] = i;
        }
    }
    // reduce 27 moment partials
    #pragma unroll
    for (int i = 0; i < 27; i++) {
        #pragma unroll
        for (int off = 16; off > 0; off >>= 1)
            s[i] += __shfl_down_sync(0xffffffffu, s[i], off);
    }
    __shared__ float part[27][8];
    int lane = threadIdx.x & 31, warp = threadIdx.x >> 5;
    if (lane == 0) {
        #pragma unroll
        for (int i = 0; i < 27; i++) part[i][warp] = s[i];
    }
    __syncthreads();
    if (threadIdx.x < 27) {
        float tot = 0.f;
        int nw = blockDim.x >> 5;
        for (int w = 0; w < nw; w++) tot += part[threadIdx.x][w];
        atomicAdd(&g_mom[threadIdx.x], (double)tot);
    }
}

// ---------------------------------------------------------------------------
// K2: fold BN into per-feature affine
// ---------------------------------------------------------------------------
__global__ void k_finalize(const float* __restrict__ W, const float* __restrict__ b,
                           const float* __restrict__ gamma, const float* __restrict__ beta,
                           double inv_n) {
    int j = threadIdx.x;
    if (j >= OUTF) return;
    double S[6], M[21], w[6];
    for (int k = 0; k < 6; k++)  S[k] = g_mom[k];
    for (int t = 0; t < 21; t++) M[t] = g_mom[6 + t];
    for (int k = 0; k < 6; k++)  w[k] = (double)W[j * 6 + k];
    double bj = (double)b[j];

    double dot = 0.0;
    for (int k = 0; k < 6; k++) dot += w[k] * S[k];
    double q = 0.0; int t = 0;
    for (int A = 0; A < 6; A++)
        for (int B = A; B < 6; B++) {
            double term = w[A] * w[B] * M[t++];
            q += (A == B) ? term : 2.0 * term;
        }
    double mean = dot * inv_n + bj;
    double e2   = (q + 2.0 * bj * dot) * inv_n + bj * bj;
    double var  = e2 - mean * mean;
    double scale = (double)gamma[j] / sqrt(var + (double)BN_EPS);

    for (int k = 0; k < 6; k++) g_Wc[k][j] = (float)(scale * w[k]);
    g_c[j] = (float)((double)beta[j] + scale * (bj - mean));
}

// ---------------------------------------------------------------------------
// K3: gather — one WARP per cell (4 cells per warp, sequential).
// Lane l owns feature pair (2l, 2l+1): weights = 6 u64 regs, loaded once.
// Payload chunk of 4 points (32 words) loaded coalesced (1 LDG.32/lane),
// point values broadcast to the warp via SHFL. Output: one STG.64 per lane.
// Every cell written unconditionally -> no memset of d_out needed.
// ---------------------------------------------------------------------------
__global__ void __launch_bounds__(256) k_gather(float* __restrict__ out) {
    int lane = threadIdx.x & 31;
    int wid  = threadIdx.x >> 5;
    int wg   = blockIdx.x * 8 + wid;        // global warp id
    int cell0 = wg * 4;

    u64 w0 = *(const u64*)&g_Wc[0][2 * lane];
    u64 w1 = *(const u64*)&g_Wc[1][2 * lane];
    u64 w2 = *(const u64*)&g_Wc[2][2 * lane];
    u64 w3 = *(const u64*)&g_Wc[3][2 * lane];
    u64 w4 = *(const u64*)&g_Wc[4][2 * lane];
    u64 w5 = *(const u64*)&g_Wc[5][2 * lane];
    u64 cp = *(const u64*)&g_c[2 * lane];

    #pragma unroll 1
    for (int c = 0; c < 4; c++) {
        int cell = cell0 + c;
        int cnt = g_count[cell];
        cnt = cnt < CAP ? cnt : CAP;
        const float* base = g_pay + ((size_t)cell << 9);   // 512 floats per cell
        float a0 = 0.f, a1 = 0.f;

        if (cnt > 0) {
            float wd = base[lane];                          // chunk 0 (4 points)
            #pragma unroll 1
            for (int p0 = 0; p0 < cnt; p0 += 4) {
                int pn = (p0 + 4 < cnt) ? p0 + 4 : p0;      // branch-free prefetch clamp
                float wn = base[pn * 8 + lane];
                int m = cnt - p0;                           // warp-uniform
                #pragma unroll
                for (int p = 0; p < 4; p++) {
                    if (p < m) {
                        float v0 = __shfl_sync(0xffffffffu, wd, p * 8 + 0);
                        float v1 = __shfl_sync(0xffffffffu, wd, p * 8 + 1);
                        float v2 = __shfl_sync(0xffffffffu, wd, p * 8 + 2);
                        float v3 = __shfl_sync(0xffffffffu, wd, p * 8 + 3);
                        float v4 = __shfl_sync(0xffffffffu, wd, p * 8 + 4);
                        float v5 = __shfl_sync(0xffffffffu, wd, p * 8 + 5);
                        u64 t = cp;
                        t = fma2(pk2(v0, v0), w0, t);
                        t = fma2(pk2(v1, v1), w1, t);
                        t = fma2(pk2(v2, v2), w2, t);
                        t = fma2(pk2(v3, v3), w3, t);
                        t = fma2(pk2(v4, v4), w4, t);
                        t = fma2(pk2(v5, v5), w5, t);
                        float lo, hi;
                        up2(t, lo, hi);
                        a0 += fmaxf(lo, 0.f);
                        a1 += fmaxf(hi, 0.f);
                    }
                }
                wd = wn;
            }
        }
        *(float2*)(out + ((size_t)cell << 6) + 2 * lane) = make_float2(a0, a1);
    }
}

// ---------------------------------------------------------------------------
// K4: overflow points (expected none) — red.v4 onto the already-written grid
// ---------------------------------------------------------------------------
__global__ void k_overflow(const float* __restrict__ x, const void* __restrict__ idx,
                           float* __restrict__ out) {
    int nov = g_ovfn; if (nov > 8192) nov = 8192;
    int is64 = g_dtype;
    for (int e = blockIdx.x * blockDim.x + threadIdx.x; e < nov;
         e += gridDim.x * blockDim.x) {
        int i = g_ovf[e];
        const float2* p = (const float2*)(x + (size_t)i * INF);
        float2 a = p[0], b = p[1], c = p[2];
        float v[6] = {a.x, a.y, b.x, b.y, c.x, c.y};
        int ix, iy;
        if (is64) {
            longlong2 id = ((const longlong2*)idx)[i];
            ix = (int)id.x; iy = (int)id.y;
        } else {
            int2 id = ((const int2*)idx)[i];
            ix = id.x; iy = id.y;
        }
        float* cellp = out + (size_t)((ix << 9) | iy) * OUTF;
        for (int jg = 0; jg < OUTF / 4; jg++) {
            int j = jg * 4;
            float4 acc = *(const float4*)&g_c[j];
            for (int k = 0; k < 6; k++) {
                acc.x = fmaf(v[k], g_Wc[k][j + 0], acc.x);
                acc.y = fmaf(v[k], g_Wc[k][j + 1], acc.y);
                acc.z = fmaf(v[k], g_Wc[k][j + 2], acc.z);
                acc.w = fmaf(v[k], g_Wc[k][j + 3], acc.w);
            }
            acc.x = fmaxf(acc.x, 0.f); acc.y = fmaxf(acc.y, 0.f);
            acc.z = fmaxf(acc.z, 0.f); acc.w = fmaxf(acc.w, 0.f);
            asm volatile("red.global.add.v4.f32 [%0], {%1, %2, %3, %4};"
                         :: "l"(cellp + j), "f"(acc.x), "f"(acc.y), "f"(acc.z), "f"(acc.w)
                         : "memory");
        }
    }
}

// ---------------------------------------------------------------------------
extern "C" void kernel_launch(void* const* d_in, const int* in_sizes, int n_in,
                              void* d_out, int out_size) {
    const float* x     = (const float*)d_in[0];
    const void*  idx   = d_in[1];
    const float* W     = (const float*)d_in[2];
    const float* b     = (const float*)d_in[3];
    const float* gamma = (const float*)d_in[4];
    const float* beta  = (const float*)d_in[5];
    float* out = (float*)d_out;

    int n = in_sizes[0] / INF;
    int nwords = 2 * n; if (nwords > 8192) nwords = 8192;

    k_init<<<256, 256>>>((const unsigned int*)idx, nwords);
    k_moments_bin<<<1184, 256>>>(x, idx, n);
    k_finalize<<<1, 64>>>(W, b, gamma, beta, 1.0 / (double)n);
    k_gather<<<NCELLS / 32, 256>>>(out);            // 8 warps/block, 4 cells/warp
    k_overflow<<<16, 256>>>(x, idx, out);
}